// round 1
// baseline (speedup 1.0000x reference)
#include <cuda_runtime.h>

#define B_    4
#define CIN_  256
#define COUT_ 256
#define CMID_ 64
#define H_    64
#define W_    64
#define HO_   128
#define WO_   128
#define KC    16

// scratch (no allocs allowed)
__device__ float g_xmid[B_ * CMID_ * H_ * W_];      // [b][m][h][w]
__device__ float g_wt_high[9 * CIN_ * COUT_];       // [tap][c][o]
__device__ float g_wt_low [9 * CMID_ * COUT_];      // [tap][m][o]

// ---------------------------------------------------------------------------
// Re-layout weights: [c][o][ky][kx] -> [tap][c][o]  (o-major for coalesced LDG)
// ---------------------------------------------------------------------------
__global__ void wt_kernel(const float* __restrict__ wh, const float* __restrict__ wl)
{
    int i = blockIdx.x * 256 + threadIdx.x;
    const int NH = 9 * CIN_ * COUT_;
    const int NL = 9 * CMID_ * COUT_;
    if (i < NH) {
        int o = i % COUT_;
        int c = (i / COUT_) % CIN_;
        int t = i / (COUT_ * CIN_);
        g_wt_high[i] = wh[(c * COUT_ + o) * 9 + t];
    } else if (i < NH + NL) {
        int j = i - NH;
        int o = j % COUT_;
        int m = (j / COUT_) % CMID_;
        int t = j / (COUT_ * CMID_);
        g_wt_low[j] = wl[(m * COUT_ + o) * 9 + t];
    }
}

// ---------------------------------------------------------------------------
// 1x1 bottleneck: xmid[b,m,hw] = sum_c w1[m,c] * inx[b,c,hw] + b1[m]
// GEMM tile: 64 m x 64 px, K chunks of 32.
// ---------------------------------------------------------------------------
__global__ __launch_bounds__(256) void mid_kernel(
    const float* __restrict__ inx, const float* __restrict__ w1,
    const float* __restrict__ b1)
{
    __shared__ float xs[32][64];
    __shared__ float ws[32][64];
    int b  = blockIdx.y;
    int p0 = blockIdx.x * 64;
    int tid = threadIdx.x;
    int tx = tid & 15, ty = tid >> 4;
    float acc[4][4] = {};
    for (int ck = 0; ck < CIN_ / 32; ck++) {
        #pragma unroll
        for (int r = 0; r < 8; r++) {
            int e = r * 256 + tid;
            int cc = e >> 6, p = e & 63;
            xs[cc][p] = inx[(b * CIN_ + ck * 32 + cc) * (H_ * W_) + p0 + p];
            ws[cc][p] = w1[p * CIN_ + ck * 32 + cc];   // p = m here
        }
        __syncthreads();
        #pragma unroll
        for (int cc = 0; cc < 32; cc++) {
            float wv[4], xv[4];
            #pragma unroll
            for (int i = 0; i < 4; i++) wv[i] = ws[cc][ty * 4 + i];
            #pragma unroll
            for (int j = 0; j < 4; j++) xv[j] = xs[cc][tx * 4 + j];
            #pragma unroll
            for (int i = 0; i < 4; i++)
                #pragma unroll
                for (int j = 0; j < 4; j++)
                    acc[i][j] += wv[i] * xv[j];
        }
        __syncthreads();
    }
    #pragma unroll
    for (int i = 0; i < 4; i++) {
        int m = ty * 4 + i;
        float bias = b1[m];
        #pragma unroll
        for (int j = 0; j < 4; j++)
            g_xmid[(b * CMID_ + m) * (H_ * W_) + p0 + tx * 4 + j] = acc[i][j] + bias;
    }
}

// ---------------------------------------------------------------------------
// Main kernel, one template instantiation per output parity class (PY, PX).
// Transposed-conv tap map (o = 2*i - 1 + k'):
//   even coord: k'=1, i=y        (1 tap)
//   odd  coord: k'=0, i=y+1 ; k'=2, i=y   (2 taps)
// Block: 64 out channels x 64 subgrid pixels (one full subgrid row).
// ---------------------------------------------------------------------------

#define CONV_BRANCH(NCH, SRCBASE, WSRC, ACC)                                       \
    for (int ck = 0; ck < (NCH) / KC; ck++) {                                      \
        for (int e = tid; e < KC * NTY * NCOL; e += 256) {                         \
            int xi = e % NCOL;                                                     \
            int rr = (e / NCOL) % NTY;                                             \
            int cc = e / (NCOL * NTY);                                             \
            int iy = y + rr;                                                       \
            float v = 0.f;                                                         \
            if (iy < H_ && xi < W_)                                                \
                v = (SRCBASE)[((size_t)(b * (NCH) + ck * KC + cc) * H_ + iy) * W_ + xi]; \
            xs[cc][rr][xi] = v;                                                    \
        }                                                                          \
        _Pragma("unroll")                                                          \
        for (int a = 0; a < NTY; a++) {                                            \
            _Pragma("unroll")                                                      \
            for (int bb = 0; bb < NTX; bb++) {                                     \
                const int ky  = PY ? (a == 0 ? 0 : 2) : 1;                         \
                const int kx  = PX ? (bb == 0 ? 0 : 2) : 1;                        \
                const int tap = ky * 3 + kx;                                       \
                const int slot = a * NTX + bb;                                     \
                for (int e = tid; e < KC * 64; e += 256) {                         \
                    int o = e & 63, cc = e >> 6;                                   \
                    ws[slot][cc][o] =                                              \
                        (WSRC)[((size_t)(tap * (NCH) + ck * KC + cc)) * COUT_ + mt * 64 + o]; \
                }                                                                  \
            }                                                                      \
        }                                                                          \
        __syncthreads();                                                           \
        _Pragma("unroll")                                                          \
        for (int cc = 0; cc < KC; cc++) {                                          \
            float xv[NTY][4 + PX];                                                 \
            _Pragma("unroll")                                                      \
            for (int r = 0; r < NTY; r++)                                          \
                _Pragma("unroll")                                                  \
                for (int j = 0; j < 4 + PX; j++)                                   \
                    xv[r][j] = xs[cc][r][x0 + j];                                  \
            _Pragma("unroll")                                                      \
            for (int a = 0; a < NTY; a++) {                                        \
                _Pragma("unroll")                                                  \
                for (int bb = 0; bb < NTX; bb++) {                                 \
                    const int slot = a * NTX + bb;                                 \
                    const int dy = PY ? (a == 0 ? 1 : 0) : 0;                      \
                    const int dx = PX ? (bb == 0 ? 1 : 0) : 0;                     \
                    float wv[4];                                                   \
                    _Pragma("unroll")                                              \
                    for (int i = 0; i < 4; i++) wv[i] = ws[slot][cc][ty * 4 + i];  \
                    _Pragma("unroll")                                              \
                    for (int i = 0; i < 4; i++)                                    \
                        _Pragma("unroll")                                          \
                        for (int j = 0; j < 4; j++)                                \
                            ACC[i][j] += wv[i] * xv[dy][j + dx];                   \
                }                                                                  \
            }                                                                      \
        }                                                                          \
        __syncthreads();                                                           \
    }

template <int PY, int PX>
__global__ __launch_bounds__(256) void main_kernel(
    const float* __restrict__ inx,
    const float* __restrict__ mask, const float* __restrict__ invmask,
    const float* __restrict__ b_high, const float* __restrict__ b_low2,
    float* __restrict__ out)
{
    constexpr int NTY  = PY ? 2 : 1;
    constexpr int NTX  = PX ? 2 : 1;
    constexpr int NT   = NTY * NTX;
    constexpr int NCOL = 64 + PX;

    __shared__ float xs[KC][NTY][NCOL];
    __shared__ float ws[NT][KC][64];

    int mt = blockIdx.x;   // out-channel tile (0..3)
    int y  = blockIdx.y;   // subgrid row (0..63)
    int b  = blockIdx.z;   // batch
    int tid = threadIdx.x;
    int tx = tid & 15, ty = tid >> 4;
    int x0 = tx * 4;
    int o0 = mt * 64 + ty * 4;

    float acc_h[4][4] = {};
    float acc_l[4][4] = {};

    CONV_BRANCH(CIN_,  inx,    g_wt_high, acc_h)
    CONV_BRANCH(CMID_, g_xmid, g_wt_low,  acc_l)

    int oy = 2 * y + PY;
    #pragma unroll
    for (int j = 0; j < 4; j++) {
        int ox = 2 * (x0 + j) + PX;
        float mk = mask[b * (HO_ * WO_) + oy * WO_ + ox];
        float im = invmask[b * (HO_ * WO_) + oy * WO_ + ox];
        #pragma unroll
        for (int i = 0; i < 4; i++) {
            int o = o0 + i;
            out[(((size_t)b * COUT_ + o) * HO_ + oy) * WO_ + ox] =
                mk * (acc_h[i][j] + b_high[o]) + im * (acc_l[i][j] + b_low2[o]);
        }
    }
}

// ---------------------------------------------------------------------------
extern "C" void kernel_launch(void* const* d_in, const int* in_sizes, int n_in,
                              void* d_out, int out_size)
{
    const float* inx  = (const float*)d_in[0];
    const float* mask = (const float*)d_in[1];
    const float* invm = (const float*)d_in[2];
    const float* wh   = (const float*)d_in[3];
    const float* bh   = (const float*)d_in[4];
    const float* w1   = (const float*)d_in[5];
    const float* b1   = (const float*)d_in[6];
    const float* wl2  = (const float*)d_in[7];
    const float* bl2  = (const float*)d_in[8];
    float* out = (float*)d_out;

    int nwt = 9 * CIN_ * COUT_ + 9 * CMID_ * COUT_;
    wt_kernel<<<(nwt + 255) / 256, 256>>>(wh, wl2);
    mid_kernel<<<dim3(H_ * W_ / 64, B_), 256>>>(inx, w1, b1);

    dim3 g(COUT_ / 64, H_, B_);
    main_kernel<0, 0><<<g, 256>>>(inx, mask, invm, bh, bl2, out);
    main_kernel<0, 1><<<g, 256>>>(inx, mask, invm, bh, bl2, out);
    main_kernel<1, 0><<<g, 256>>>(inx, mask, invm, bh, bl2, out);
    main_kernel<1, 1><<<g, 256>>>(inx, mask, invm, bh, bl2, out);
}

// round 5
// speedup vs baseline: 3.5862x; 3.5862x over previous
#include <cuda_runtime.h>
#include <cstdint>

#define B_    4
#define CIN_  256
#define COUT_ 256
#define CMID_ 64
#define H_    64
#define W_    64
#define HO_   128
#define WO_   128

// ---------------------------------------------------------------------------
// scratch (static __device__ — no allocs allowed)
// ---------------------------------------------------------------------------
__device__ __align__(128) float g_inxT [B_ * H_ * W_ * CIN_];   // [b][y][x][c]  tf32-rounded
__device__ __align__(128) float g_xmidT[B_ * H_ * W_ * CMID_];  // [b][y][x][m]  tf32-rounded
__device__ __align__(128) float g_wtH  [9 * COUT_ * CIN_];      // [tap][o][c]   tf32-rounded
__device__ __align__(128) float g_wtL  [9 * COUT_ * CMID_];     // [tap][o][m]   tf32-rounded

__device__ __forceinline__ float to_tf32(float x) {
    float y; asm("cvt.rna.tf32.f32 %0, %1;" : "=f"(y) : "f"(x)); return y;
}
__device__ __forceinline__ uint32_t smem_u32(const void* p) {
    uint32_t a;
    asm("{ .reg .u64 t; cvta.to.shared.u64 t, %1; cvt.u32.u64 %0, t; }" : "=r"(a) : "l"(p));
    return a;
}

#define SWZ(off) ((uint32_t)(off) ^ ((((uint32_t)(off)) >> 3) & 0x70))

#define CP_ASYNC16(dst, src) \
    asm volatile("cp.async.ca.shared.global [%0], [%1], 16;" :: "r"(dst), "l"(src) : "memory")
#define CP_COMMIT() asm volatile("cp.async.commit_group;" ::: "memory")
#define CP_WAIT0()  asm volatile("cp.async.wait_group 0;" ::: "memory")

#define MMA_TF32(c, a, bf)                                                        \
    asm volatile("mma.sync.aligned.m16n8k8.row.col.f32.tf32.tf32.f32 "            \
        "{%0,%1,%2,%3}, {%4,%5,%6,%7}, {%8,%9}, {%0,%1,%2,%3};"                   \
        : "+f"((c)[0]), "+f"((c)[1]), "+f"((c)[2]), "+f"((c)[3])                  \
        : "r"((a)[0]), "r"((a)[1]), "r"((a)[2]), "r"((a)[3]),                     \
          "r"((bf)[0]), "r"((bf)[1]))

// dynamic SMEM layout (bytes)
#define SM_A      0          // 2 x 16KB
#define SM_B      32768      // 2 x 16KB
#define SM_MSK    65536      // s_mh[128], s_ml[128]
#define SMEM_BYTES (65536 + 1024)

// ---------------------------------------------------------------------------
// prep: weights -> [tap][o][c] (tf32-rounded)
// ---------------------------------------------------------------------------
__global__ void wt_kernel(const float* __restrict__ wh, const float* __restrict__ wl)
{
    int i = blockIdx.x * 256 + threadIdx.x;
    const int NH = 9 * COUT_ * CIN_;
    const int NL = 9 * COUT_ * CMID_;
    if (i < NH) {
        int c = i & 255, o = (i >> 8) & 255, t = i >> 16;
        g_wtH[i] = to_tf32(wh[(c * COUT_ + o) * 9 + t]);
    } else if (i < NH + NL) {
        int j = i - NH;
        int m = j & 63, o = (j >> 6) & 255, t = j >> 14;
        g_wtL[j] = to_tf32(wl[(m * COUT_ + o) * 9 + t]);
    }
}

// ---------------------------------------------------------------------------
// prep: inx [b][c][y][x] -> inxT [b][y][x][c] (tf32-rounded)
// ---------------------------------------------------------------------------
__global__ __launch_bounds__(256) void transpose_kernel(const float* __restrict__ inx)
{
    __shared__ float sm[64][65];
    int y = blockIdx.x, c0 = blockIdx.y * 64, b = blockIdx.z;
    int tid = threadIdx.x;
    #pragma unroll
    for (int it = 0; it < 16; it++) {
        int e = it * 256 + tid;
        int cr = e >> 6, x = e & 63;
        sm[cr][x] = inx[((size_t)(b * CIN_ + c0 + cr) * H_ + y) * W_ + x];
    }
    __syncthreads();
    #pragma unroll
    for (int it = 0; it < 16; it++) {
        int e = it * 256 + tid;
        int x = e >> 6, c = e & 63;
        g_inxT[((size_t)((b * H_ + y) * W_ + x)) * CIN_ + c0 + c] = to_tf32(sm[c][x]);
    }
}

// ---------------------------------------------------------------------------
// prep: 1x1 bottleneck (fp32 exact) -> xmidT [b][y][x][m] (tf32-rounded)
// ---------------------------------------------------------------------------
__global__ __launch_bounds__(256) void mid_kernel(
    const float* __restrict__ inx, const float* __restrict__ w1, const float* __restrict__ b1)
{
    __shared__ float xs[32][64];
    __shared__ float ws[32][64];
    int b = blockIdx.y;
    int p0 = blockIdx.x * 64;
    int tid = threadIdx.x;
    int tx = tid & 15, ty = tid >> 4;
    float acc[4][4] = {};
    for (int ck = 0; ck < CIN_ / 32; ck++) {
        #pragma unroll
        for (int r = 0; r < 8; r++) {
            int e = r * 256 + tid;
            int cc = e >> 6, p = e & 63;
            xs[cc][p] = inx[(b * CIN_ + ck * 32 + cc) * (H_ * W_) + p0 + p];
            ws[cc][p] = w1[p * CIN_ + ck * 32 + cc];
        }
        __syncthreads();
        #pragma unroll
        for (int cc = 0; cc < 32; cc++) {
            float wv[4], xv[4];
            #pragma unroll
            for (int i = 0; i < 4; i++) wv[i] = ws[cc][ty * 4 + i];
            #pragma unroll
            for (int j = 0; j < 4; j++) xv[j] = xs[cc][tx * 4 + j];
            #pragma unroll
            for (int i = 0; i < 4; i++)
                #pragma unroll
                for (int j = 0; j < 4; j++)
                    acc[i][j] += wv[i] * xv[j];
        }
        __syncthreads();
    }
    #pragma unroll
    for (int j = 0; j < 4; j++) {
        float4 v;
        v.x = to_tf32(acc[0][j] + b1[ty * 4 + 0]);
        v.y = to_tf32(acc[1][j] + b1[ty * 4 + 1]);
        v.z = to_tf32(acc[2][j] + b1[ty * 4 + 2]);
        v.w = to_tf32(acc[3][j] + b1[ty * 4 + 3]);
        *(float4*)&g_xmidT[((size_t)(b * (H_ * W_) + p0 + tx * 4 + j)) * CMID_ + ty * 4] = v;
    }
}

// ---------------------------------------------------------------------------
// main mma.sync kernel: grid (mt=2, ypair=32, 16), block 256 (8 warps, 2x4)
// single fused GEMM: D = Wh·(mask⊙Xh) + Wl·(inv⊙Xl); K = 320*T, chunks of 32
// ---------------------------------------------------------------------------
__global__ __launch_bounds__(256) void tconv_mma_kernel(
    const float* __restrict__ mask, const float* __restrict__ invm,
    const float* __restrict__ bh, const float* __restrict__ bl,
    float* __restrict__ out)
{
    extern __shared__ __align__(16) char smem[];
    const uint32_t sbase = smem_u32(smem);
    float* s_mh = (float*)(smem + SM_MSK);
    float* s_ml = (float*)(smem + SM_MSK + 512);

    const int tid = threadIdx.x, lane = tid & 31, wid = tid >> 5;
    const int lr = lane >> 2, lc = lane & 3;
    const int wm = wid >> 2, wn = wid & 3;      // warp grid 2 x 4
    const int m0w = wm * 64, n0w = wn * 32;

    const int o0 = blockIdx.x * 128;
    const int y0 = blockIdx.y * 2;
    const int z = blockIdx.z, b = z & 3;
    const int permc[4] = {3, 1, 2, 0};          // heavy class first
    const int cls = permc[z >> 2];
    const int PY = cls >> 1, PX = cls & 1;
    const int TXn = 1 + PX;
    const int T = (1 + PY) * (1 + PX);
    const int NC = 10 * T;                       // 8T high + 2T low chunks of K=32

    // preload masks for this block's 128 output pixels
    if (tid < 128) {
        int r = tid >> 6, xi = tid & 63;
        int oy = 2 * (y0 + r) + PY, ox = 2 * xi + PX;
        s_mh[tid] = mask[(b * HO_ + oy) * WO_ + ox];
        s_ml[tid] = invm[(b * HO_ + oy) * WO_ + ox];
    }
    __syncthreads();

    float acc[4][4][4];
    #pragma unroll
    for (int i = 0; i < 4; i++)
        #pragma unroll
        for (int j = 0; j < 4; j++)
            #pragma unroll
            for (int k = 0; k < 4; k++) acc[i][j][k] = 0.f;

    // chunk decode state
    const float* src = g_inxT;
    const float* wp = g_wtH;
    int CH = CIN_, dy = 0, dx = 0, cur_cc = 0;
    bool high = true;

    auto decode = [&](int i) {
        high = (i < 8 * T);
        int tap;
        if (high) { tap = i >> 3; cur_cc = (i & 7) * 32; CH = CIN_;  src = g_inxT;  }
        else      { int j = i - 8 * T; tap = j >> 1; cur_cc = (j & 1) * 32; CH = CMID_; src = g_xmidT; }
        int tyi = tap / TXn, txi = tap % TXn;
        int ky = PY ? (tyi ? 2 : 0) : 1;  dy = PY ? (tyi ? 0 : 1) : 0;
        int kx = PX ? (txi ? 2 : 0) : 1;  dx = PX ? (txi ? 0 : 1) : 0;
        const float* wbase = high ? g_wtH : g_wtL;
        wp = wbase + ((size_t)((ky * 3 + kx) * COUT_ + o0)) * CH + cur_cc;
    };

    float4 pb[4];  // B prefetch regs (mask-scaled before STS)

    auto issueA = [&](int buf) {
        uint32_t dstb = sbase + SM_A + buf * 16384;
        #pragma unroll
        for (int it = 0; it < 4; it++) {
            int e = it * 256 + tid;
            int m = e >> 3, f = e & 7;
            CP_ASYNC16(dstb + SWZ(m * 128 + f * 16), wp + (size_t)m * CH + f * 4);
        }
        CP_COMMIT();
    };
    auto issueB = [&]() {
        const float* sp = src + cur_cc;
        #pragma unroll
        for (int it = 0; it < 4; it++) {
            int e = it * 256 + tid;
            int n = e >> 3, f = e & 7;
            int iy = y0 + (n >> 6) + dy, ix = (n & 63) + dx;
            float4 v = make_float4(0.f, 0.f, 0.f, 0.f);
            if (iy < H_ && ix < W_)
                v = *(const float4*)(sp + ((size_t)((b * H_ + iy) * W_ + ix)) * CH + f * 4);
            float mfac = high ? s_mh[n] : s_ml[n];
            v.x *= mfac; v.y *= mfac; v.z *= mfac; v.w *= mfac;
            pb[it] = v;
        }
    };

    // prologue
    decode(0);
    issueA(0);
    issueB();

    for (int i = 0; i < NC; i++) {
        int buf = i & 1;
        CP_WAIT0();
        // store B_i (mask-scaled) into smem
        {
            char* dstb = smem + SM_B + buf * 16384;
            #pragma unroll
            for (int it = 0; it < 4; it++) {
                int e = it * 256 + tid;
                int n = e >> 3, f = e & 7;
                *(float4*)(dstb + SWZ(n * 128 + f * 16)) = pb[it];
            }
        }
        __syncthreads();

        if (i + 1 < NC) {
            decode(i + 1);
            issueA(buf ^ 1);
            issueB();
        }

        // compute chunk i
        const char* Ab = smem + SM_A + buf * 16384;
        const char* Bb = smem + SM_B + buf * 16384;
        #pragma unroll
        for (int ks = 0; ks < 4; ks++) {
            uint32_t a[4][4], bf[4][2];
            #pragma unroll
            for (int mt = 0; mt < 4; mt++) {
                int row = m0w + mt * 16 + lr;
                int s = row & 7;
                int f0 = ((ks * 2) ^ s) * 16 + lc * 4;
                int f1 = ((ks * 2 + 1) ^ s) * 16 + lc * 4;
                a[mt][0] = *(const uint32_t*)(Ab + row * 128 + f0);
                a[mt][1] = *(const uint32_t*)(Ab + (row + 8) * 128 + f0);
                a[mt][2] = *(const uint32_t*)(Ab + row * 128 + f1);
                a[mt][3] = *(const uint32_t*)(Ab + (row + 8) * 128 + f1);
            }
            #pragma unroll
            for (int nt = 0; nt < 4; nt++) {
                int nr = n0w + nt * 8 + lr;
                int s = nr & 7;
                bf[nt][0] = *(const uint32_t*)(Bb + nr * 128 + (((ks * 2) ^ s) * 16 + lc * 4));
                bf[nt][1] = *(const uint32_t*)(Bb + nr * 128 + (((ks * 2 + 1) ^ s) * 16 + lc * 4));
            }
            #pragma unroll
            for (int mt = 0; mt < 4; mt++)
                #pragma unroll
                for (int nt = 0; nt < 4; nt++)
                    MMA_TF32(acc[mt][nt], a[mt], bf[nt]);
        }
        __syncthreads();
    }

    // epilogue: out = acc + mask*bh + inv*bl
    #pragma unroll
    for (int mt = 0; mt < 4; mt++) {
        int o_lo = o0 + m0w + mt * 16 + lr;
        int o_hi = o_lo + 8;
        float bh0 = bh[o_lo], bl0 = bl[o_lo];
        float bh1 = bh[o_hi], bl1 = bl[o_hi];
        #pragma unroll
        for (int nt = 0; nt < 4; nt++) {
            #pragma unroll
            for (int rg = 0; rg < 4; rg++) {
                int n = n0w + nt * 8 + 2 * lc + (rg & 1);
                int o = (rg < 2) ? o_lo : o_hi;
                float bhv = (rg < 2) ? bh0 : bh1;
                float blv = (rg < 2) ? bl0 : bl1;
                int r = n >> 6, xi = n & 63;
                int oy = 2 * (y0 + r) + PY, ox = 2 * xi + PX;
                out[(((size_t)b * COUT_ + o) * HO_ + oy) * WO_ + ox] =
                    acc[mt][nt][rg] + s_mh[n] * bhv + s_ml[n] * blv;
            }
        }
    }
}

// ---------------------------------------------------------------------------
extern "C" void kernel_launch(void* const* d_in, const int* in_sizes, int n_in,
                              void* d_out, int out_size)
{
    const float* inx  = (const float*)d_in[0];
    const float* mask = (const float*)d_in[1];
    const float* invm = (const float*)d_in[2];
    const float* wh   = (const float*)d_in[3];
    const float* bh   = (const float*)d_in[4];
    const float* w1   = (const float*)d_in[5];
    const float* b1   = (const float*)d_in[6];
    const float* wl2  = (const float*)d_in[7];
    const float* bl2  = (const float*)d_in[8];
    float* out = (float*)d_out;

    cudaFuncSetAttribute(tconv_mma_kernel,
                         cudaFuncAttributeMaxDynamicSharedMemorySize, SMEM_BYTES);

    int nwt = 9 * COUT_ * CIN_ + 9 * COUT_ * CMID_;
    wt_kernel<<<(nwt + 255) / 256, 256>>>(wh, wl2);
    transpose_kernel<<<dim3(H_, 4, B_), 256>>>(inx);
    mid_kernel<<<dim3(H_ * W_ / 64, B_), 256>>>(inx, w1, b1);

    tconv_mma_kernel<<<dim3(2, 32, 16), 256, SMEM_BYTES>>>(mask, invm, bh, bl2, out);
}

// round 6
// speedup vs baseline: 4.3197x; 1.2045x over previous
#include <cuda_runtime.h>
#include <cstdint>

#define B_    4
#define CIN_  256
#define COUT_ 256
#define CMID_ 64
#define H_    64
#define W_    64
#define HO_   128
#define WO_   128

// ---------------------------------------------------------------------------
// scratch (static __device__ — no allocs allowed)
// ---------------------------------------------------------------------------
__device__ __align__(128) float g_inxT [B_ * H_ * W_ * CIN_];   // [b][y][x][c]  tf32-rounded
__device__ __align__(128) float g_xmidT[B_ * H_ * W_ * CMID_];  // [b][y][x][m]  tf32-rounded
__device__ __align__(128) float g_wtH  [9 * COUT_ * CIN_];      // [tap][o][c]   tf32-rounded
__device__ __align__(128) float g_wtL  [9 * COUT_ * CMID_];     // [tap][o][m]   tf32-rounded

__device__ __forceinline__ float to_tf32(float x) {
    float y; asm("cvt.rna.tf32.f32 %0, %1;" : "=f"(y) : "f"(x)); return y;
}
__device__ __forceinline__ uint32_t smem_u32(const void* p) {
    uint32_t a;
    asm("{ .reg .u64 t; cvta.to.shared.u64 t, %1; cvt.u32.u64 %0, t; }" : "=r"(a) : "l"(p));
    return a;
}

#define SWZ(off) ((uint32_t)(off) ^ ((((uint32_t)(off)) >> 3) & 0x70))

#define CP_ASYNC16(dst, src) \
    asm volatile("cp.async.ca.shared.global [%0], [%1], 16;" :: "r"(dst), "l"(src) : "memory")
#define CP_COMMIT() asm volatile("cp.async.commit_group;" ::: "memory")
#define CP_WAIT0()  asm volatile("cp.async.wait_group 0;" ::: "memory")

#define MMA_TF32(c, a, bf)                                                        \
    asm volatile("mma.sync.aligned.m16n8k8.row.col.f32.tf32.tf32.f32 "            \
        "{%0,%1,%2,%3}, {%4,%5,%6,%7}, {%8,%9}, {%0,%1,%2,%3};"                   \
        : "+f"((c)[0]), "+f"((c)[1]), "+f"((c)[2]), "+f"((c)[3])                  \
        : "r"((a)[0]), "r"((a)[1]), "r"((a)[2]), "r"((a)[3]),                     \
          "r"((bf)[0]), "r"((bf)[1]))

// dynamic SMEM layout (bytes): A 2x16KB | B 2x8KB | masks
#define SM_A      0
#define SM_B      32768
#define SM_MSK    49152
#define SMEM_BYTES (49152 + 512)

// ---------------------------------------------------------------------------
// fused prep kernel:
//   blocks [0,1024)        : transpose inx -> g_inxT (channel-last, tf32)
//   blocks [1024,1280)     : 1x1 bottleneck (fp32) -> g_xmidT (tf32)
//   blocks [1280,1280+2880): weights -> [tap][o][c] (tf32)
// ---------------------------------------------------------------------------
__global__ __launch_bounds__(256) void prep_kernel(
    const float* __restrict__ inx,
    const float* __restrict__ wh, const float* __restrict__ wl,
    const float* __restrict__ w1, const float* __restrict__ b1)
{
    __shared__ float sbuf[64 * 65];
    const int bid = blockIdx.x;
    const int tid = threadIdx.x;

    if (bid < 1024) {
        // --- transpose: [b][c][y][x] -> [b][y][x][c]
        int y = bid & 63, c0 = ((bid >> 6) & 3) * 64, b = bid >> 8;
        #pragma unroll
        for (int it = 0; it < 16; it++) {
            int e = it * 256 + tid;
            int cr = e >> 6, x = e & 63;
            sbuf[cr * 65 + x] = inx[((size_t)(b * CIN_ + c0 + cr) * H_ + y) * W_ + x];
        }
        __syncthreads();
        #pragma unroll
        for (int it = 0; it < 16; it++) {
            int e = it * 256 + tid;
            int x = e >> 6, c = e & 63;
            g_inxT[((size_t)((b * H_ + y) * W_ + x)) * CIN_ + c0 + c] = to_tf32(sbuf[c * 65 + x]);
        }
    } else if (bid < 1280) {
        // --- 1x1 bottleneck GEMM (exact fp32), 64 m x 64 px tile
        float* xs = sbuf;            // [32][64]
        float* ws = sbuf + 2048;     // [32][64]
        int id = bid - 1024;
        int b = id >> 6;
        int p0 = (id & 63) * 64;
        int tx = tid & 15, ty = tid >> 4;
        float acc[4][4] = {};
        for (int ck = 0; ck < CIN_ / 32; ck++) {
            #pragma unroll
            for (int r = 0; r < 8; r++) {
                int e = r * 256 + tid;
                int cc = e >> 6, p = e & 63;
                xs[cc * 64 + p] = inx[(b * CIN_ + ck * 32 + cc) * (H_ * W_) + p0 + p];
                ws[cc * 64 + p] = w1[p * CIN_ + ck * 32 + cc];
            }
            __syncthreads();
            #pragma unroll
            for (int cc = 0; cc < 32; cc++) {
                float wv[4], xv[4];
                #pragma unroll
                for (int i = 0; i < 4; i++) wv[i] = ws[cc * 64 + ty * 4 + i];
                #pragma unroll
                for (int j = 0; j < 4; j++) xv[j] = xs[cc * 64 + tx * 4 + j];
                #pragma unroll
                for (int i = 0; i < 4; i++)
                    #pragma unroll
                    for (int j = 0; j < 4; j++)
                        acc[i][j] += wv[i] * xv[j];
            }
            __syncthreads();
        }
        #pragma unroll
        for (int j = 0; j < 4; j++) {
            float4 v;
            v.x = to_tf32(acc[0][j] + b1[ty * 4 + 0]);
            v.y = to_tf32(acc[1][j] + b1[ty * 4 + 1]);
            v.z = to_tf32(acc[2][j] + b1[ty * 4 + 2]);
            v.w = to_tf32(acc[3][j] + b1[ty * 4 + 3]);
            *(float4*)&g_xmidT[((size_t)(b * (H_ * W_) + p0 + tx * 4 + j)) * CMID_ + ty * 4] = v;
        }
    } else {
        // --- weight re-layout
        int i = (bid - 1280) * 256 + tid;
        const int NH = 9 * COUT_ * CIN_;
        const int NL = 9 * COUT_ * CMID_;
        if (i < NH) {
            int c = i & 255, o = (i >> 8) & 255, t = i >> 16;
            g_wtH[i] = to_tf32(wh[(c * COUT_ + o) * 9 + t]);
        } else if (i < NH + NL) {
            int j = i - NH;
            int m = j & 63, o = (j >> 6) & 255, t = j >> 14;
            g_wtL[j] = to_tf32(wl[(m * COUT_ + o) * 9 + t]);
        }
    }
}

// ---------------------------------------------------------------------------
// main mma.sync kernel: grid (mt=2, y=64, 16), block 128 (4 warps, 2x2)
// block tile M=128 (cout) x N=64 (one subgrid row); warp tile 64x32
// single fused GEMM: D = Wh·(mask⊙Xh) + Wl·(inv⊙Xl); K = 320*T, chunks of 32
// ---------------------------------------------------------------------------
__global__ __launch_bounds__(128, 3) void tconv_mma_kernel(
    const float* __restrict__ mask, const float* __restrict__ invm,
    const float* __restrict__ bh, const float* __restrict__ bl,
    float* __restrict__ out)
{
    extern __shared__ __align__(16) char smem[];
    const uint32_t sbase = smem_u32(smem);
    float* s_mh = (float*)(smem + SM_MSK);
    float* s_ml = (float*)(smem + SM_MSK + 256);

    const int tid = threadIdx.x, lane = tid & 31, wid = tid >> 5;
    const int lr = lane >> 2, lc = lane & 3;
    const int wm = wid >> 1, wn = wid & 1;      // warp grid 2 x 2
    const int m0w = wm * 64, n0w = wn * 32;

    const int o0 = blockIdx.x * 128;
    const int y0 = blockIdx.y;                  // one subgrid row
    const int z = blockIdx.z, b = z & 3;
    const int permc[4] = {3, 1, 2, 0};          // heavy class first
    const int cls = permc[z >> 2];
    const int PY = cls >> 1, PX = cls & 1;
    const int TXn = 1 + PX;
    const int T = (1 + PY) * (1 + PX);
    const int NC = 10 * T;                      // 8T high + 2T low chunks of K=32

    // preload masks for this block's 64 output pixels
    if (tid < 64) {
        int oy = 2 * y0 + PY, ox = 2 * tid + PX;
        s_mh[tid] = mask[(b * HO_ + oy) * WO_ + ox];
        s_ml[tid] = invm[(b * HO_ + oy) * WO_ + ox];
    }
    __syncthreads();

    float acc[4][4][4];
    #pragma unroll
    for (int i = 0; i < 4; i++)
        #pragma unroll
        for (int j = 0; j < 4; j++)
            #pragma unroll
            for (int k = 0; k < 4; k++) acc[i][j][k] = 0.f;

    // chunk decode state
    const float* src = g_inxT;
    const float* wp = g_wtH;
    int CH = CIN_, dy = 0, dx = 0, cur_cc = 0;
    bool high = true;

    auto decode = [&](int i) {
        high = (i < 8 * T);
        int tap;
        if (high) { tap = i >> 3; cur_cc = (i & 7) * 32; CH = CIN_;  src = g_inxT;  }
        else      { int j = i - 8 * T; tap = j >> 1; cur_cc = (j & 1) * 32; CH = CMID_; src = g_xmidT; }
        int tyi = tap / TXn, txi = tap % TXn;
        int ky = PY ? (tyi ? 2 : 0) : 1;  dy = PY ? (tyi ? 0 : 1) : 0;
        int kx = PX ? (txi ? 2 : 0) : 1;  dx = PX ? (txi ? 0 : 1) : 0;
        const float* wbase = high ? g_wtH : g_wtL;
        wp = wbase + ((size_t)((ky * 3 + kx) * COUT_ + o0)) * CH + cur_cc;
    };

    float4 pb[4];  // B prefetch regs (mask-scaled before STS)

    auto issueA = [&](int buf) {
        uint32_t dstb = sbase + SM_A + buf * 16384;
        #pragma unroll
        for (int it = 0; it < 8; it++) {
            int e = it * 128 + tid;
            int m = e >> 3, f = e & 7;
            CP_ASYNC16(dstb + SWZ(m * 128 + f * 16), wp + (size_t)m * CH + f * 4);
        }
        CP_COMMIT();
    };
    auto issueB = [&]() {
        const float* sp = src + cur_cc;
        int iy = y0 + dy;
        #pragma unroll
        for (int it = 0; it < 4; it++) {
            int e = it * 128 + tid;
            int n = e >> 3, f = e & 7;
            int ix = n + dx;
            float4 v = make_float4(0.f, 0.f, 0.f, 0.f);
            if (iy < H_ && ix < W_)
                v = *(const float4*)(sp + ((size_t)((b * H_ + iy) * W_ + ix)) * CH + f * 4);
            float mfac = high ? s_mh[n] : s_ml[n];
            v.x *= mfac; v.y *= mfac; v.z *= mfac; v.w *= mfac;
            pb[it] = v;
        }
    };

    // prologue
    decode(0);
    issueA(0);
    issueB();

    for (int i = 0; i < NC; i++) {
        int buf = i & 1;
        CP_WAIT0();
        // store B_i (mask-scaled) into smem
        {
            char* dstb = smem + SM_B + buf * 8192;
            #pragma unroll
            for (int it = 0; it < 4; it++) {
                int e = it * 128 + tid;
                int n = e >> 3, f = e & 7;
                *(float4*)(dstb + SWZ(n * 128 + f * 16)) = pb[it];
            }
        }
        __syncthreads();   // single barrier per chunk (double-buffer safe)

        if (i + 1 < NC) {
            decode(i + 1);
            issueA(buf ^ 1);
            issueB();
        }

        // compute chunk i
        const char* Ab = smem + SM_A + buf * 16384;
        const char* Bb = smem + SM_B + buf * 8192;
        #pragma unroll
        for (int ks = 0; ks < 4; ks++) {
            uint32_t a[4][4], bf[4][2];
            #pragma unroll
            for (int mt = 0; mt < 4; mt++) {
                int row = m0w + mt * 16 + lr;
                int s = row & 7;
                int f0 = ((ks * 2) ^ s) * 16 + lc * 4;
                int f1 = ((ks * 2 + 1) ^ s) * 16 + lc * 4;
                a[mt][0] = *(const uint32_t*)(Ab + row * 128 + f0);
                a[mt][1] = *(const uint32_t*)(Ab + (row + 8) * 128 + f0);
                a[mt][2] = *(const uint32_t*)(Ab + row * 128 + f1);
                a[mt][3] = *(const uint32_t*)(Ab + (row + 8) * 128 + f1);
            }
            #pragma unroll
            for (int nt = 0; nt < 4; nt++) {
                int nr = n0w + nt * 8 + lr;
                int s = nr & 7;
                bf[nt][0] = *(const uint32_t*)(Bb + nr * 128 + (((ks * 2) ^ s) * 16 + lc * 4));
                bf[nt][1] = *(const uint32_t*)(Bb + nr * 128 + (((ks * 2 + 1) ^ s) * 16 + lc * 4));
            }
            #pragma unroll
            for (int mt = 0; mt < 4; mt++)
                #pragma unroll
                for (int nt = 0; nt < 4; nt++)
                    MMA_TF32(acc[mt][nt], a[mt], bf[nt]);
        }
        // no trailing barrier: iter i+1's mid-chunk barrier orders reuse
    }

    // epilogue: out = acc + mask*bh + inv*bl
    const int oy = 2 * y0 + PY;
    #pragma unroll
    for (int mt = 0; mt < 4; mt++) {
        int o_lo = o0 + m0w + mt * 16 + lr;
        int o_hi = o_lo + 8;
        float bh0 = bh[o_lo], bl0 = bl[o_lo];
        float bh1 = bh[o_hi], bl1 = bl[o_hi];
        #pragma unroll
        for (int nt = 0; nt < 4; nt++) {
            #pragma unroll
            for (int rg = 0; rg < 4; rg++) {
                int n = n0w + nt * 8 + 2 * lc + (rg & 1);
                int o = (rg < 2) ? o_lo : o_hi;
                float bhv = (rg < 2) ? bh0 : bh1;
                float blv = (rg < 2) ? bl0 : bl1;
                int ox = 2 * n + PX;
                out[(((size_t)b * COUT_ + o) * HO_ + oy) * WO_ + ox] =
                    acc[mt][nt][rg] + s_mh[n] * bhv + s_ml[n] * blv;
            }
        }
    }
}

// ---------------------------------------------------------------------------
extern "C" void kernel_launch(void* const* d_in, const int* in_sizes, int n_in,
                              void* d_out, int out_size)
{
    const float* inx  = (const float*)d_in[0];
    const float* mask = (const float*)d_in[1];
    const float* invm = (const float*)d_in[2];
    const float* wh   = (const float*)d_in[3];
    const float* bh   = (const float*)d_in[4];
    const float* w1   = (const float*)d_in[5];
    const float* b1   = (const float*)d_in[6];
    const float* wl2  = (const float*)d_in[7];
    const float* bl2  = (const float*)d_in[8];
    float* out = (float*)d_out;

    cudaFuncSetAttribute(tconv_mma_kernel,
                         cudaFuncAttributeMaxDynamicSharedMemorySize, SMEM_BYTES);

    // prep: 1024 transpose + 256 mid + 2880 weight blocks
    prep_kernel<<<1024 + 256 + 2880, 256>>>(inx, wh, wl2, w1, b1);

    tconv_mma_kernel<<<dim3(2, 64, 16), 128, SMEM_BYTES>>>(mask, invm, bh, bl2, out);
}

// round 8
// speedup vs baseline: 4.4720x; 1.0352x over previous
#include <cuda_runtime.h>
#include <cstdint>

#define B_    4
#define CIN_  256
#define COUT_ 256
#define CMID_ 64
#define H_    64
#define W_    64
#define HO_   128
#define WO_   128

// ---------------------------------------------------------------------------
// scratch (static __device__ — no allocs allowed)
// ---------------------------------------------------------------------------
__device__ __align__(128) float g_inxT [B_ * H_ * W_ * CIN_];   // [b][y][x][c]  tf32-rounded
__device__ __align__(128) float g_xmidT[B_ * H_ * W_ * CMID_];  // [b][y][x][m]  tf32-rounded
__device__ __align__(128) float g_wtH  [9 * COUT_ * CIN_];      // [tap][o][c]   tf32-rounded
__device__ __align__(128) float g_wtL  [9 * COUT_ * CMID_];     // [tap][o][m]   tf32-rounded

__device__ __forceinline__ float to_tf32(float x) {
    float y; asm("cvt.rna.tf32.f32 %0, %1;" : "=f"(y) : "f"(x)); return y;
}
__device__ __forceinline__ uint32_t smem_u32(const void* p) {
    uint32_t a;
    asm("{ .reg .u64 t; cvta.to.shared.u64 t, %1; cvt.u32.u64 %0, t; }" : "=r"(a) : "l"(p));
    return a;
}

#define SWZ(off) ((uint32_t)(off) ^ ((((uint32_t)(off)) >> 3) & 0x70))

#define CP_ASYNC16(dst, src) \
    asm volatile("cp.async.ca.shared.global [%0], [%1], 16;" :: "r"(dst), "l"(src) : "memory")
#define CP_COMMIT() asm volatile("cp.async.commit_group;" ::: "memory")
#define CP_WAIT0()  asm volatile("cp.async.wait_group 0;" ::: "memory")

#define MMA_TF32(c, a, bf)                                                        \
    asm volatile("mma.sync.aligned.m16n8k8.row.col.f32.tf32.tf32.f32 "            \
        "{%0,%1,%2,%3}, {%4,%5,%6,%7}, {%8,%9}, {%0,%1,%2,%3};"                   \
        : "+f"((c)[0]), "+f"((c)[1]), "+f"((c)[2]), "+f"((c)[3])                  \
        : "r"((a)[0]), "r"((a)[1]), "r"((a)[2]), "r"((a)[3]),                     \
          "r"((bf)[0]), "r"((bf)[1]))

// dynamic SMEM layout (bytes): A 2x16KB | B 2x16KB | masks
#define SM_A      0
#define SM_B      32768
#define SM_MSK    65536
#define SMEM_BYTES (65536 + 1024)

// ---------------------------------------------------------------------------
// fused prep kernel:
//   blocks [0,1024)        : transpose inx -> g_inxT (channel-last, tf32)
//   blocks [1024,1280)     : 1x1 bottleneck (fp32) -> g_xmidT (tf32)
//   blocks [1280,1280+2880): weights -> [tap][o][c] (coalesced read, scat write)
// ---------------------------------------------------------------------------
__global__ __launch_bounds__(256) void prep_kernel(
    const float* __restrict__ inx,
    const float* __restrict__ wh, const float* __restrict__ wl,
    const float* __restrict__ w1, const float* __restrict__ b1)
{
    __shared__ float sbuf[64 * 65];
    const int bid = blockIdx.x;
    const int tid = threadIdx.x;

    if (bid < 1024) {
        // --- transpose: [b][c][y][x] -> [b][y][x][c]
        int y = bid & 63, c0 = ((bid >> 6) & 3) * 64, b = bid >> 8;
        #pragma unroll
        for (int it = 0; it < 16; it++) {
            int e = it * 256 + tid;
            int cr = e >> 6, x = e & 63;
            sbuf[cr * 65 + x] = inx[((size_t)(b * CIN_ + c0 + cr) * H_ + y) * W_ + x];
        }
        __syncthreads();
        #pragma unroll
        for (int it = 0; it < 16; it++) {
            int e = it * 256 + tid;
            int x = e >> 6, c = e & 63;
            g_inxT[((size_t)((b * H_ + y) * W_ + x)) * CIN_ + c0 + c] = to_tf32(sbuf[c * 65 + x]);
        }
    } else if (bid < 1280) {
        // --- 1x1 bottleneck GEMM (exact fp32), 64 m x 64 px tile
        float* xs = sbuf;            // [32][64]
        float* ws = sbuf + 2048;     // [32][64]
        int id = bid - 1024;
        int b = id >> 6;
        int p0 = (id & 63) * 64;
        int tx = tid & 15, ty = tid >> 4;
        float acc[4][4] = {};
        for (int ck = 0; ck < CIN_ / 32; ck++) {
            #pragma unroll
            for (int r = 0; r < 8; r++) {
                int e = r * 256 + tid;
                int cc = e >> 6, p = e & 63;
                xs[cc * 64 + p] = inx[(b * CIN_ + ck * 32 + cc) * (H_ * W_) + p0 + p];
                ws[cc * 64 + p] = w1[p * CIN_ + ck * 32 + cc];
            }
            __syncthreads();
            #pragma unroll
            for (int cc = 0; cc < 32; cc++) {
                float wv[4], xv[4];
                #pragma unroll
                for (int i = 0; i < 4; i++) wv[i] = ws[cc * 64 + ty * 4 + i];
                #pragma unroll
                for (int j = 0; j < 4; j++) xv[j] = xs[cc * 64 + tx * 4 + j];
                #pragma unroll
                for (int i = 0; i < 4; i++)
                    #pragma unroll
                    for (int j = 0; j < 4; j++)
                        acc[i][j] += wv[i] * xv[j];
            }
            __syncthreads();
        }
        #pragma unroll
        for (int j = 0; j < 4; j++) {
            float4 v;
            v.x = to_tf32(acc[0][j] + b1[ty * 4 + 0]);
            v.y = to_tf32(acc[1][j] + b1[ty * 4 + 1]);
            v.z = to_tf32(acc[2][j] + b1[ty * 4 + 2]);
            v.w = to_tf32(acc[3][j] + b1[ty * 4 + 3]);
            *(float4*)&g_xmidT[((size_t)(b * (H_ * W_) + p0 + tx * 4 + j)) * CMID_ + ty * 4] = v;
        }
    } else {
        // --- weight re-layout: coalesced READ, scattered write to [tap][o][c]
        int i = (bid - 1280) * 256 + tid;
        const int NH = 9 * COUT_ * CIN_;
        const int NL = 9 * COUT_ * CMID_;
        if (i < NH) {
            // i = (c*COUT + o)*9 + t  (source linear order)
            int t = i % 9;
            int co = i / 9;
            int o = co & 255, c = co >> 8;
            g_wtH[(t * COUT_ + o) * CIN_ + c] = to_tf32(wh[i]);   // [tap][o][c]
        } else if (i < NH + NL) {
            int j = i - NH;
            int t = j % 9;
            int mo = j / 9;
            int o = mo & 255, m = mo >> 8;
            g_wtL[(t * COUT_ + o) * CMID_ + m] = to_tf32(wl[j]);  // [tap][o][m]
        }
    }
}

// ---------------------------------------------------------------------------
// main mma.sync kernel: grid (mt=2, ypair=32, 16), block 128 (4 warps, 2x2)
// block tile M=128 (cout) x N=128 (two subgrid rows); warp tile 64x64
// single fused GEMM: D = Wh·(mask⊙Xh) + Wl·(inv⊙Xl); K = 320*T, chunks of 32
// ---------------------------------------------------------------------------
__global__ __launch_bounds__(128, 2) void tconv_mma_kernel(
    const float* __restrict__ mask, const float* __restrict__ invm,
    const float* __restrict__ bh, const float* __restrict__ bl,
    float* __restrict__ out)
{
    extern __shared__ __align__(16) char smem[];
    const uint32_t sbase = smem_u32(smem);
    float* s_mh = (float*)(smem + SM_MSK);
    float* s_ml = (float*)(smem + SM_MSK + 512);

    const int tid = threadIdx.x, lane = tid & 31, wid = tid >> 5;
    const int lr = lane >> 2, lc = lane & 3;
    const int wm = wid >> 1, wn = wid & 1;      // warp grid 2 x 2
    const int m0w = wm * 64, n0w = wn * 64;

    const int o0 = blockIdx.x * 128;
    const int y0 = blockIdx.y * 2;              // two subgrid rows
    const int z = blockIdx.z, b = z & 3;
    const int permc[4] = {3, 1, 2, 0};          // heavy class first
    const int cls = permc[z >> 2];
    const int PY = cls >> 1, PX = cls & 1;
    const int TXn = 1 + PX;
    const int T = (1 + PY) * (1 + PX);
    const int NC = 10 * T;                      // 8T high + 2T low chunks of K=32

    // preload masks for this block's 128 output pixels
    if (tid < 128) {
        int r = tid >> 6, xi = tid & 63;
        int oy = 2 * (y0 + r) + PY, ox = 2 * xi + PX;
        s_mh[tid] = mask[(b * HO_ + oy) * WO_ + ox];
        s_ml[tid] = invm[(b * HO_ + oy) * WO_ + ox];
    }
    __syncthreads();

    float acc[4][8][4];
    #pragma unroll
    for (int i = 0; i < 4; i++)
        #pragma unroll
        for (int j = 0; j < 8; j++)
            #pragma unroll
            for (int k = 0; k < 4; k++) acc[i][j][k] = 0.f;

    // chunk decode state
    const float* src = g_inxT;
    const float* wp = g_wtH;
    int CH = CIN_, dy = 0, dx = 0, cur_cc = 0;
    bool high = true;

    auto decode = [&](int i) {
        high = (i < 8 * T);
        int tap;
        if (high) { tap = i >> 3; cur_cc = (i & 7) * 32; CH = CIN_;  src = g_inxT;  }
        else      { int j = i - 8 * T; tap = j >> 1; cur_cc = (j & 1) * 32; CH = CMID_; src = g_xmidT; }
        int tyi = tap / TXn, txi = tap % TXn;
        int ky = PY ? (tyi ? 2 : 0) : 1;  dy = PY ? (tyi ? 0 : 1) : 0;
        int kx = PX ? (txi ? 2 : 0) : 1;  dx = PX ? (txi ? 0 : 1) : 0;
        const float* wbase = high ? g_wtH : g_wtL;
        wp = wbase + ((size_t)((ky * 3 + kx) * COUT_ + o0)) * CH + cur_cc;
    };

    float4 pb[8];  // B prefetch regs (mask-scaled before STS)

    auto issueA = [&](int buf) {
        uint32_t dstb = sbase + SM_A + buf * 16384;
        #pragma unroll
        for (int it = 0; it < 8; it++) {
            int e = it * 128 + tid;
            int m = e >> 3, f = e & 7;
            CP_ASYNC16(dstb + SWZ(m * 128 + f * 16), wp + (size_t)m * CH + f * 4);
        }
        CP_COMMIT();
    };
    auto issueB = [&]() {
        const float* sp = src + cur_cc;
        #pragma unroll
        for (int it = 0; it < 8; it++) {
            int e = it * 128 + tid;
            int n = e >> 3, f = e & 7;
            int iy = y0 + (n >> 6) + dy, ix = (n & 63) + dx;
            float4 v = make_float4(0.f, 0.f, 0.f, 0.f);
            if (iy < H_ && ix < W_)
                v = *(const float4*)(sp + ((size_t)((b * H_ + iy) * W_ + ix)) * CH + f * 4);
            float mfac = high ? s_mh[n] : s_ml[n];
            v.x *= mfac; v.y *= mfac; v.z *= mfac; v.w *= mfac;
            pb[it] = v;
        }
    };

    // prologue
    decode(0);
    issueA(0);
    issueB();

    for (int i = 0; i < NC; i++) {
        int buf = i & 1;
        CP_WAIT0();
        // store B_i (mask-scaled) into smem
        {
            char* dstb = smem + SM_B + buf * 16384;
            #pragma unroll
            for (int it = 0; it < 8; it++) {
                int e = it * 128 + tid;
                int n = e >> 3, f = e & 7;
                *(float4*)(dstb + SWZ(n * 128 + f * 16)) = pb[it];
            }
        }
        __syncthreads();   // single barrier per chunk (double-buffer safe)

        if (i + 1 < NC) {
            decode(i + 1);
            issueA(buf ^ 1);
            issueB();
        }

        // compute chunk i
        const char* Ab = smem + SM_A + buf * 16384;
        const char* Bb = smem + SM_B + buf * 16384;
        #pragma unroll
        for (int ks = 0; ks < 4; ks++) {
            uint32_t a[4][4], bf[8][2];
            #pragma unroll
            for (int mt = 0; mt < 4; mt++) {
                int row = m0w + mt * 16 + lr;
                int s = row & 7;
                int f0 = ((ks * 2) ^ s) * 16 + lc * 4;
                int f1 = ((ks * 2 + 1) ^ s) * 16 + lc * 4;
                a[mt][0] = *(const uint32_t*)(Ab + row * 128 + f0);
                a[mt][1] = *(const uint32_t*)(Ab + (row + 8) * 128 + f0);
                a[mt][2] = *(const uint32_t*)(Ab + row * 128 + f1);
                a[mt][3] = *(const uint32_t*)(Ab + (row + 8) * 128 + f1);
            }
            #pragma unroll
            for (int nt = 0; nt < 8; nt++) {
                int nr = n0w + nt * 8 + lr;
                int s = nr & 7;
                bf[nt][0] = *(const uint32_t*)(Bb + nr * 128 + (((ks * 2) ^ s) * 16 + lc * 4));
                bf[nt][1] = *(const uint32_t*)(Bb + nr * 128 + (((ks * 2 + 1) ^ s) * 16 + lc * 4));
            }
            #pragma unroll
            for (int mt = 0; mt < 4; mt++)
                #pragma unroll
                for (int nt = 0; nt < 8; nt++)
                    MMA_TF32(acc[mt][nt], a[mt], bf[nt]);
        }
        // no trailing barrier: iter i+1's mid-chunk barrier orders reuse
    }

    // epilogue: out = acc + mask*bh + inv*bl
    #pragma unroll
    for (int mt = 0; mt < 4; mt++) {
        int o_lo = o0 + m0w + mt * 16 + lr;
        int o_hi = o_lo + 8;
        float bh0 = bh[o_lo], bl0 = bl[o_lo];
        float bh1 = bh[o_hi], bl1 = bl[o_hi];
        #pragma unroll
        for (int nt = 0; nt < 8; nt++) {
            #pragma unroll
            for (int rg = 0; rg < 4; rg++) {
                int n = n0w + nt * 8 + 2 * lc + (rg & 1);
                int o = (rg < 2) ? o_lo : o_hi;
                float bhv = (rg < 2) ? bh0 : bh1;
                float blv = (rg < 2) ? bl0 : bl1;
                int r = n >> 6, xi = n & 63;
                int oy = 2 * (y0 + r) + PY, ox = 2 * xi + PX;
                out[(((size_t)b * COUT_ + o) * HO_ + oy) * WO_ + ox] =
                    acc[mt][nt][rg] + s_mh[n] * bhv + s_ml[n] * blv;
            }
        }
    }
}

// ---------------------------------------------------------------------------
extern "C" void kernel_launch(void* const* d_in, const int* in_sizes, int n_in,
                              void* d_out, int out_size)
{
    const float* inx  = (const float*)d_in[0];
    const float* mask = (const float*)d_in[1];
    const float* invm = (const float*)d_in[2];
    const float* wh   = (const float*)d_in[3];
    const float* bh   = (const float*)d_in[4];
    const float* w1   = (const float*)d_in[5];
    const float* b1   = (const float*)d_in[6];
    const float* wl2  = (const float*)d_in[7];
    const float* bl2  = (const float*)d_in[8];
    float* out = (float*)d_out;

    cudaFuncSetAttribute(tconv_mma_kernel,
                         cudaFuncAttributeMaxDynamicSharedMemorySize, SMEM_BYTES);

    // prep: 1024 transpose + 256 mid + 2880 weight blocks
    prep_kernel<<<1024 + 256 + 2880, 256>>>(inx, wh, wl2, w1, b1);

    tconv_mma_kernel<<<dim3(2, 32, 16), 128, SMEM_BYTES>>>(mask, invm, bh, bl2, out);
}

// round 9
// speedup vs baseline: 4.6670x; 1.0436x over previous
#include <cuda_runtime.h>
#include <cstdint>

#define B_    4
#define CIN_  256
#define COUT_ 256
#define CMID_ 64
#define H_    64
#define W_    64
#define HO_   128
#define WO_   128

// ---------------------------------------------------------------------------
// scratch (static __device__ — no allocs allowed)
// ---------------------------------------------------------------------------
__device__ __align__(128) float g_inxT [B_ * H_ * W_ * CIN_];   // [b][y][x][c]  tf32-rounded
__device__ __align__(128) float g_xmidT[B_ * H_ * W_ * CMID_];  // [b][y][x][m]  tf32-rounded
__device__ __align__(128) float g_wtH  [9 * COUT_ * CIN_];      // [tap][o][c]   tf32-rounded
__device__ __align__(128) float g_wtL  [9 * COUT_ * CMID_];     // [tap][o][m]   tf32-rounded

__device__ __forceinline__ float to_tf32(float x) {
    float y; asm("cvt.rna.tf32.f32 %0, %1;" : "=f"(y) : "f"(x)); return y;
}
__device__ __forceinline__ uint32_t smem_u32(const void* p) {
    uint32_t a;
    asm("{ .reg .u64 t; cvta.to.shared.u64 t, %1; cvt.u32.u64 %0, t; }" : "=r"(a) : "l"(p));
    return a;
}

#define SWZ(off) ((uint32_t)(off) ^ ((((uint32_t)(off)) >> 3) & 0x70))

#define CP_ASYNC16(dst, src) \
    asm volatile("cp.async.ca.shared.global [%0], [%1], 16;" :: "r"(dst), "l"(src) : "memory")
// zero-fill form: src_size=0 -> 16 bytes of zeros
#define CP_ASYNC16Z(dst, src, sz) \
    asm volatile("cp.async.ca.shared.global [%0], [%1], 16, %2;" :: "r"(dst), "l"(src), "r"(sz) : "memory")
#define CP_COMMIT() asm volatile("cp.async.commit_group;" ::: "memory")
#define CP_WAIT0()  asm volatile("cp.async.wait_group 0;" ::: "memory")

#define MMA_TF32(c, a, bf)                                                        \
    asm volatile("mma.sync.aligned.m16n8k8.row.col.f32.tf32.tf32.f32 "            \
        "{%0,%1,%2,%3}, {%4,%5,%6,%7}, {%8,%9}, {%0,%1,%2,%3};"                   \
        : "+f"((c)[0]), "+f"((c)[1]), "+f"((c)[2]), "+f"((c)[3])                  \
        : "r"((a)[0]), "r"((a)[1]), "r"((a)[2]), "r"((a)[3]),                     \
          "r"((bf)[0]), "r"((bf)[1]))

// dynamic SMEM layout (bytes): A 2x16KB | B 2x16KB | masks
#define SM_A      0
#define SM_B      32768
#define SM_MSK    65536
#define SMEM_BYTES (65536 + 1024)

// ---------------------------------------------------------------------------
// fused prep kernel (unchanged from R8)
// ---------------------------------------------------------------------------
__global__ __launch_bounds__(256) void prep_kernel(
    const float* __restrict__ inx,
    const float* __restrict__ wh, const float* __restrict__ wl,
    const float* __restrict__ w1, const float* __restrict__ b1)
{
    __shared__ float sbuf[64 * 65];
    const int bid = blockIdx.x;
    const int tid = threadIdx.x;

    if (bid < 1024) {
        int y = bid & 63, c0 = ((bid >> 6) & 3) * 64, b = bid >> 8;
        #pragma unroll
        for (int it = 0; it < 16; it++) {
            int e = it * 256 + tid;
            int cr = e >> 6, x = e & 63;
            sbuf[cr * 65 + x] = inx[((size_t)(b * CIN_ + c0 + cr) * H_ + y) * W_ + x];
        }
        __syncthreads();
        #pragma unroll
        for (int it = 0; it < 16; it++) {
            int e = it * 256 + tid;
            int x = e >> 6, c = e & 63;
            g_inxT[((size_t)((b * H_ + y) * W_ + x)) * CIN_ + c0 + c] = to_tf32(sbuf[c * 65 + x]);
        }
    } else if (bid < 1280) {
        float* xs = sbuf;            // [32][64]
        float* ws = sbuf + 2048;     // [32][64]
        int id = bid - 1024;
        int b = id >> 6;
        int p0 = (id & 63) * 64;
        int tx = tid & 15, ty = tid >> 4;
        float acc[4][4] = {};
        for (int ck = 0; ck < CIN_ / 32; ck++) {
            #pragma unroll
            for (int r = 0; r < 8; r++) {
                int e = r * 256 + tid;
                int cc = e >> 6, p = e & 63;
                xs[cc * 64 + p] = inx[(b * CIN_ + ck * 32 + cc) * (H_ * W_) + p0 + p];
                ws[cc * 64 + p] = w1[p * CIN_ + ck * 32 + cc];
            }
            __syncthreads();
            #pragma unroll
            for (int cc = 0; cc < 32; cc++) {
                float wv[4], xv[4];
                #pragma unroll
                for (int i = 0; i < 4; i++) wv[i] = ws[cc * 64 + ty * 4 + i];
                #pragma unroll
                for (int j = 0; j < 4; j++) xv[j] = xs[cc * 64 + tx * 4 + j];
                #pragma unroll
                for (int i = 0; i < 4; i++)
                    #pragma unroll
                    for (int j = 0; j < 4; j++)
                        acc[i][j] += wv[i] * xv[j];
            }
            __syncthreads();
        }
        #pragma unroll
        for (int j = 0; j < 4; j++) {
            float4 v;
            v.x = to_tf32(acc[0][j] + b1[ty * 4 + 0]);
            v.y = to_tf32(acc[1][j] + b1[ty * 4 + 1]);
            v.z = to_tf32(acc[2][j] + b1[ty * 4 + 2]);
            v.w = to_tf32(acc[3][j] + b1[ty * 4 + 3]);
            *(float4*)&g_xmidT[((size_t)(b * (H_ * W_) + p0 + tx * 4 + j)) * CMID_ + ty * 4] = v;
        }
    } else {
        int i = (bid - 1280) * 256 + tid;
        const int NH = 9 * COUT_ * CIN_;
        const int NL = 9 * COUT_ * CMID_;
        if (i < NH) {
            int t = i % 9;
            int co = i / 9;
            int o = co & 255, c = co >> 8;
            g_wtH[(t * COUT_ + o) * CIN_ + c] = to_tf32(wh[i]);   // [tap][o][c]
        } else if (i < NH + NL) {
            int j = i - NH;
            int t = j % 9;
            int mo = j / 9;
            int o = mo & 255, m = mo >> 8;
            g_wtL[(t * COUT_ + o) * CMID_ + m] = to_tf32(wl[j]);  // [tap][o][m]
        }
    }
}

// ---------------------------------------------------------------------------
// main mma.sync kernel: grid (mt=2, ypair=32, 16), block 256 (8 warps, 2x4)
// block tile M=128 x N=128; warp tile 64x32
// phase 1 (8T chunks): acc = Wh·Xh (raw, pure cp.async)
// mid-scale:           acc *= mask[n]   (registers; mask in {0,1} -> exact)
// phase 2 (2T chunks): acc += Wl·(inv⊙Xl)  (B reg-staged, inv-scaled)
// ---------------------------------------------------------------------------
__global__ __launch_bounds__(256, 2) void tconv_mma_kernel(
    const float* __restrict__ mask, const float* __restrict__ invm,
    const float* __restrict__ bh, const float* __restrict__ bl,
    float* __restrict__ out)
{
    extern __shared__ __align__(16) char smem[];
    const uint32_t sbase = smem_u32(smem);
    float* s_mh = (float*)(smem + SM_MSK);
    float* s_ml = (float*)(smem + SM_MSK + 512);

    const int tid = threadIdx.x, lane = tid & 31, wid = tid >> 5;
    const int lr = lane >> 2, lc = lane & 3;
    const int wm = wid >> 2, wn = wid & 3;      // warp grid 2 x 4
    const int m0w = wm * 64, n0w = wn * 32;

    const int o0 = blockIdx.x * 128;
    const int y0 = blockIdx.y * 2;              // two subgrid rows
    const int z = blockIdx.z, b = z & 3;
    const int permc[4] = {3, 1, 2, 0};          // heavy class first
    const int cls = permc[z >> 2];
    const int PY = cls >> 1, PX = cls & 1;
    const int TXn = 1 + PX;
    const int T = (1 + PY) * (1 + PX);
    const int NCH = 8 * T;                      // high chunks (K=32 each)
    const int NC = 10 * T;                      // + 2T low chunks

    // preload masks for this block's 128 output pixels
    if (tid < 128) {
        int r = tid >> 6, xi = tid & 63;
        int oy = 2 * (y0 + r) + PY, ox = 2 * xi + PX;
        s_mh[tid] = mask[(b * HO_ + oy) * WO_ + ox];
        s_ml[tid] = invm[(b * HO_ + oy) * WO_ + ox];
    }
    __syncthreads();

    float acc[4][4][4];
    #pragma unroll
    for (int i = 0; i < 4; i++)
        #pragma unroll
        for (int j = 0; j < 4; j++)
            #pragma unroll
            for (int k = 0; k < 4; k++) acc[i][j][k] = 0.f;

    // chunk decode state
    const float* src = g_inxT;
    const float* wp = g_wtH;
    int CH = CIN_, dy = 0, dx = 0, cur_cc = 0;
    bool high = true;

    auto decode = [&](int i) {
        high = (i < NCH);
        int tap;
        if (high) { tap = i >> 3; cur_cc = (i & 7) * 32; CH = CIN_;  src = g_inxT;  }
        else      { int j = i - NCH; tap = j >> 1; cur_cc = (j & 1) * 32; CH = CMID_; src = g_xmidT; }
        int tyi = tap / TXn, txi = tap % TXn;
        int ky = PY ? (tyi ? 2 : 0) : 1;  dy = PY ? (tyi ? 0 : 1) : 0;
        int kx = PX ? (txi ? 2 : 0) : 1;  dx = PX ? (txi ? 0 : 1) : 0;
        const float* wbase = high ? g_wtH : g_wtL;
        wp = wbase + ((size_t)((ky * 3 + kx) * COUT_ + o0)) * CH + cur_cc;
    };

    float4 pb[4];  // B staging for LOW chunks only (inv-scaled)

    auto issueA = [&](int buf) {
        uint32_t dstb = sbase + SM_A + buf * 16384;
        #pragma unroll
        for (int it = 0; it < 4; it++) {
            int e = it * 256 + tid;
            int m = e >> 3, f = e & 7;
            CP_ASYNC16(dstb + SWZ(m * 128 + f * 16), wp + (size_t)m * CH + f * 4);
        }
    };
    // high-phase B: raw, pure cp.async with zero-fill for OOB taps
    auto issueB_async = [&](int buf) {
        uint32_t dstb = sbase + SM_B + buf * 16384;
        const float* sp = src + cur_cc;
        #pragma unroll
        for (int it = 0; it < 4; it++) {
            int e = it * 256 + tid;
            int n = e >> 3, f = e & 7;
            int iy = y0 + (n >> 6) + dy, ix = (n & 63) + dx;
            bool ok = (iy < H_) & (ix < W_);
            const float* s = sp + ((size_t)((b * H_ + (ok ? iy : 0)) * W_ + (ok ? ix : 0))) * CH + f * 4;
            CP_ASYNC16Z(dstb + SWZ(n * 128 + f * 16), s, ok ? 16u : 0u);
        }
    };
    // low-phase B: reg-staged, scaled by inv-mask
    auto issueB_reg = [&]() {
        const float* sp = src + cur_cc;
        #pragma unroll
        for (int it = 0; it < 4; it++) {
            int e = it * 256 + tid;
            int n = e >> 3, f = e & 7;
            int iy = y0 + (n >> 6) + dy, ix = (n & 63) + dx;
            float4 v = make_float4(0.f, 0.f, 0.f, 0.f);
            if (iy < H_ && ix < W_)
                v = *(const float4*)(sp + ((size_t)((b * H_ + iy) * W_ + ix)) * CH + f * 4);
            float mfac = s_ml[n];
            v.x *= mfac; v.y *= mfac; v.z *= mfac; v.w *= mfac;
            pb[it] = v;
        }
    };

    // prologue: chunk 0 is always high
    decode(0);
    issueA(0);
    issueB_async(0);
    CP_COMMIT();

    for (int i = 0; i < NC; i++) {
        int buf = i & 1;
        bool cur_high = (i < NCH);
        CP_WAIT0();
        if (!cur_high) {
            // store staged low-B (inv-scaled) into smem
            char* dstb = smem + SM_B + buf * 16384;
            #pragma unroll
            for (int it = 0; it < 4; it++) {
                int e = it * 256 + tid;
                int n = e >> 3, f = e & 7;
                *(float4*)(dstb + SWZ(n * 128 + f * 16)) = pb[it];
            }
        }
        __syncthreads();

        if (i + 1 < NC) {
            decode(i + 1);
            issueA(buf ^ 1);
            if (high) issueB_async(buf ^ 1);   // 'high' now refers to chunk i+1
            else      issueB_reg();
            CP_COMMIT();
        }

        // transition high -> low: fold mask into accumulators (exact, mask in {0,1})
        if (i == NCH) {
            #pragma unroll
            for (int nt = 0; nt < 4; nt++)
                #pragma unroll
                for (int h = 0; h < 2; h++) {
                    float mfac = s_mh[n0w + nt * 8 + 2 * lc + h];
                    #pragma unroll
                    for (int mt = 0; mt < 4; mt++) {
                        acc[mt][nt][h]     *= mfac;
                        acc[mt][nt][2 + h] *= mfac;
                    }
                }
        }

        // compute chunk i
        const char* Ab = smem + SM_A + buf * 16384;
        const char* Bb = smem + SM_B + buf * 16384;
        #pragma unroll
        for (int ks = 0; ks < 4; ks++) {
            uint32_t a[4][4], bf[4][2];
            #pragma unroll
            for (int mt = 0; mt < 4; mt++) {
                int row = m0w + mt * 16 + lr;
                int s = row & 7;
                int f0 = ((ks * 2) ^ s) * 16 + lc * 4;
                int f1 = ((ks * 2 + 1) ^ s) * 16 + lc * 4;
                a[mt][0] = *(const uint32_t*)(Ab + row * 128 + f0);
                a[mt][1] = *(const uint32_t*)(Ab + (row + 8) * 128 + f0);
                a[mt][2] = *(const uint32_t*)(Ab + row * 128 + f1);
                a[mt][3] = *(const uint32_t*)(Ab + (row + 8) * 128 + f1);
            }
            #pragma unroll
            for (int nt = 0; nt < 4; nt++) {
                int nr = n0w + nt * 8 + lr;
                int s = nr & 7;
                bf[nt][0] = *(const uint32_t*)(Bb + nr * 128 + (((ks * 2) ^ s) * 16 + lc * 4));
                bf[nt][1] = *(const uint32_t*)(Bb + nr * 128 + (((ks * 2 + 1) ^ s) * 16 + lc * 4));
            }
            #pragma unroll
            for (int mt = 0; mt < 4; mt++)
                #pragma unroll
                for (int nt = 0; nt < 4; nt++)
                    MMA_TF32(acc[mt][nt], a[mt], bf[nt]);
        }
        // no trailing barrier: next iter's mid-chunk barrier orders reuse
    }

    // epilogue: out = acc + mask*bh + inv*bl
    #pragma unroll
    for (int mt = 0; mt < 4; mt++) {
        int o_lo = o0 + m0w + mt * 16 + lr;
        int o_hi = o_lo + 8;
        float bh0 = bh[o_lo], bl0 = bl[o_lo];
        float bh1 = bh[o_hi], bl1 = bl[o_hi];
        #pragma unroll
        for (int nt = 0; nt < 4; nt++) {
            #pragma unroll
            for (int rg = 0; rg < 4; rg++) {
                int n = n0w + nt * 8 + 2 * lc + (rg & 1);
                int o = (rg < 2) ? o_lo : o_hi;
                float bhv = (rg < 2) ? bh0 : bh1;
                float blv = (rg < 2) ? bl0 : bl1;
                int r = n >> 6, xi = n & 63;
                int oy = 2 * (y0 + r) + PY, ox = 2 * xi + PX;
                out[(((size_t)b * COUT_ + o) * HO_ + oy) * WO_ + ox] =
                    acc[mt][nt][rg] + s_mh[n] * bhv + s_ml[n] * blv;
            }
        }
    }
}

// ---------------------------------------------------------------------------
extern "C" void kernel_launch(void* const* d_in, const int* in_sizes, int n_in,
                              void* d_out, int out_size)
{
    const float* inx  = (const float*)d_in[0];
    const float* mask = (const float*)d_in[1];
    const float* invm = (const float*)d_in[2];
    const float* wh   = (const float*)d_in[3];
    const float* bh   = (const float*)d_in[4];
    const float* w1   = (const float*)d_in[5];
    const float* b1   = (const float*)d_in[6];
    const float* wl2  = (const float*)d_in[7];
    const float* bl2  = (const float*)d_in[8];
    float* out = (float*)d_out;

    cudaFuncSetAttribute(tconv_mma_kernel,
                         cudaFuncAttributeMaxDynamicSharedMemorySize, SMEM_BYTES);

    // prep: 1024 transpose + 256 mid + 2880 weight blocks
    prep_kernel<<<1024 + 256 + 2880, 256>>>(inx, wh, wl2, w1, b1);

    tconv_mma_kernel<<<dim3(2, 32, 16), 256, SMEM_BYTES>>>(mask, invm, bh, bl2, out);
}